// round 12
// baseline (speedup 1.0000x reference)
#include <cuda_runtime.h>
#include <cuda_bf16.h>

// Problem geometry: [B=4, 1, D=160, H=160, W=160]
#define NB 4
#define S  160
#define PLANE4  6400               // float4/int4 per (b,d) plane
#define NPLANES 640
#define CHUNK4  800
#define N4      4096000            // total float4 quads
#define BATCH4  1024000            // quads per batch
#define NT      320                // threads per block (320 % 40 == 0)
#define TOTAL_ELEMS (4.0 * 160.0 * 160.0 * 160.0)

// ---- device scratch (zero at load; last block re-zeroes flags/counter) ----
__device__ unsigned char g_winD[NB][8];   // boundary-slab any-flags (0..3 low, 4..7 high)
__device__ unsigned char g_winH[NB][8];
__device__ unsigned char g_winW[NB][8];
__device__ double g_planeSS[NPLANES];     // per-plane sum of (p-t)^2
__device__ float  g_row159[NPLANES];      // per-plane sum over row h=159
__device__ float  g_col159[NPLANES];      // per-plane sum over col w=159
__device__ float  g_e1599[NPLANES];       // per-plane element (159,159)
__device__ unsigned g_done;

// Exact f32 replication of the reference bbox math (mn<0 -> empty box).
__device__ __forceinline__ void bbox_from(int mn, int mx, int* lo, int* hi) {
    if (mn < 0) { *lo = 0; *hi = 0; return; }
    float c = ((float)mx + (float)mn) * 0.5f;
    float e = ((float)mx - (float)mn + 1.0f) * 0.5f * 1.2f;   // EXPAND
    *lo = (int)fmaxf(0.0f, floorf(c - e));
    *hi = (int)fminf((float)(S - 1), floorf(c + e));          // EXCLUSIVE
}

// ============================================================================
// Single kernel. One block per (b,d) plane, 640 x 320 (5 blocks/SM -> 78% occ,
// one wave). 320 % 40 == 0, so each thread owns a FIXED W-column c = tid%40:
// the w=159 slab is a fixed-predicate lane (c==39), and the h=159 slab lives
// only in the peeled last iteration (rows 152..159).
// Last-done block: if every axis has fg in both 4-wide boundary windows, the
// reference box is PROVABLY [0,159)^3 (mn<=3, mx>=156 => c-e<0, c+e>159), so
// the ROI complement is the three index-159 slabs and the loss follows by
// inclusion-exclusion over the per-plane tables. Otherwise an exact
// single-block fallback runs (correct for ALL inputs).
// ============================================================================
__global__ __launch_bounds__(NT, 5) void k_all(const float* __restrict__ pred,
                                               const float* __restrict__ truth,
                                               const int*   __restrict__ mask,
                                               float* __restrict__ out) {
    __shared__ double wAcc[10], wRow[10], wCol[10];
    __shared__ int sw[8];
    __shared__ int sLast;
    __shared__ unsigned char sFlags[96];
    __shared__ double sRed[10][8];

    const int p    = blockIdx.x;         // 0..639
    const int b    = p / S;
    const int tid  = threadIdx.x;
    const int c    = tid % 40;           // fixed W-column (int4 granularity)
    const int hrow = tid / 40;           // 0..7

    if (tid < 8) sw[tid] = 0;
    __syncthreads();

    // ---- mask boundary windows (one load per thread; issued first) ----
    const int4* M = (const int4*)mask + (size_t)p * PLANE4;
    {
        // H window: 160 quads at each end; thread t<160 -> low end, else high
        int hq = (tid < 160) ? tid : (6240 + tid - 160);
        int4 va = M[hq];
        if (va.x | va.y | va.z | va.w) {
            int slot = (tid < 160) ? (tid / 40) : (4 + (tid - 160) / 40);
            g_winH[b][slot] = 1;
        }
        // W window: row r = tid%160, side = tid/160 (first/last int4 of row)
        int r    = (tid < 160) ? tid : tid - 160;
        int side = (tid < 160) ? 0 : 1;
        int4 v0 = M[r * 40 + side * 39];
        if (v0.x) sw[side * 4 + 0] = 1;
        if (v0.y) sw[side * 4 + 1] = 1;
        if (v0.z) sw[side * 4 + 2] = 1;
        if (v0.w) sw[side * 4 + 3] = 1;
    }
    // D window: blocks 0..255 each scan one 800-int4 chunk of a boundary plane
    if (blockIdx.x < 256) {
        int item = blockIdx.x;
        int bb   = item >> 6;
        int wp   = (item >> 3) & 7;
        int part = item & 7;
        int dd   = (wp < 4) ? wp : 152 + wp;
        const int4* MD = (const int4*)mask + (size_t)(bb * S + dd) * PLANE4 + part * CHUNK4;
        int o = 0;
        for (int j = tid; j < CHUNK4; j += NT) {
            int4 v = MD[j];
            o |= v.x | v.y | v.z | v.w;
        }
        if (__syncthreads_or(o)) { if (tid == 0) g_winD[bb][wp] = 1; }
    }

    // ---- streaming SS pass: 20 iterations, last one peeled for h=159 ----
    const float4* P = (const float4*)pred  + (size_t)p * PLANE4;
    const float4* T = (const float4*)truth + (size_t)p * PLANE4;
    const bool lastCol = (c == 39);      // this thread's .w lane is w = 159

    float acc = 0.0f, accRow = 0.0f, accCol = 0.0f, e1599 = 0.0f;
    #pragma unroll 5
    for (int k = 0; k < 19; k++) {
        int i = tid + NT * k;
        float4 pv = P[i];
        float4 tv = T[i];
        float dx = pv.x - tv.x, dy = pv.y - tv.y;
        float dz = pv.z - tv.z, dw = pv.w - tv.w;
        float q = dx * dx;
        q = fmaf(dy, dy, q);
        q = fmaf(dz, dz, q);
        q = fmaf(dw, dw, q);
        acc += q;
        if (lastCol) accCol = fmaf(dw, dw, accCol);   // column w = 159
    }
    {   // k = 19: rows 152..159; h = 159 <=> hrow == 7
        int i = tid + NT * 19;
        float4 pv = P[i];
        float4 tv = T[i];
        float dx = pv.x - tv.x, dy = pv.y - tv.y;
        float dz = pv.z - tv.z, dw = pv.w - tv.w;
        float q = dx * dx;
        q = fmaf(dy, dy, q);
        q = fmaf(dz, dz, q);
        q = fmaf(dw, dw, q);
        acc += q;
        float w2 = dw * dw;
        if (lastCol) accCol += w2;
        if (hrow == 7) accRow += q;                   // row h = 159
        if (lastCol && hrow == 7) e1599 = w2;         // (159,159)
    }

    __syncthreads();
    if (tid < 8 && sw[tid]) g_winW[b][tid] = 1;

    // ---- reduce; store per-plane tables ----
    #pragma unroll
    for (int off = 16; off > 0; off >>= 1) {
        acc    += __shfl_xor_sync(0xFFFFFFFFu, acc,    off);
        accRow += __shfl_xor_sync(0xFFFFFFFFu, accRow, off);
        accCol += __shfl_xor_sync(0xFFFFFFFFu, accCol, off);
    }
    const int lane = tid & 31, wid = tid >> 5;
    if (lane == 0) {
        wAcc[wid] = (double)acc;
        wRow[wid] = (double)accRow;
        wCol[wid] = (double)accCol;
    }
    __syncthreads();
    if (tid == 0) {
        double sa = 0.0, sr = 0.0, sc = 0.0;
        #pragma unroll
        for (int w = 0; w < 10; w++) { sa += wAcc[w]; sr += wRow[w]; sc += wCol[w]; }
        g_planeSS[p] = sa;
        g_row159[p]  = (float)sr;
        g_col159[p]  = (float)sc;
    }
    if (tid == NT - 1) g_e1599[p] = e1599;            // owns i = 6399

    // ---- threadFenceReduction ticket: last-done block finalizes ----
    __threadfence();
    __syncthreads();
    if (tid == 0) sLast = (atomicAdd(&g_done, 1u) == (unsigned)(NPLANES - 1));
    __syncthreads();
    if (!sLast) return;

    // parallel window-flag fetch
    if (tid < 32)      sFlags[tid] = ((const unsigned char*)g_winD)[tid];
    else if (tid < 64) sFlags[tid] = ((const unsigned char*)g_winH)[tid - 32];
    else if (tid < 96) sFlags[tid] = ((const unsigned char*)g_winW)[tid - 64];
    __syncthreads();

    bool resolved = true;
    #pragma unroll
    for (int bb = 0; bb < NB; bb++) {
        #pragma unroll
        for (int ax = 0; ax < 3; ax++) {
            const unsigned char* f = &sFlags[ax * 32 + bb * 8];
            int loAny = f[0] | f[1] | f[2] | f[3];
            int hiAny = f[4] | f[5] | f[6] | f[7];
            if (!loAny || !hiAny) resolved = false;
        }
    }

    if (resolved) {
        // box = [0,159)^3 for every batch: inclusion-exclusion over tables
        double v[8];                     // ssAll, D, H, W, DH, DW, HW, DHW
        #pragma unroll
        for (int q = 0; q < 8; q++) v[q] = 0.0;
        for (int pp = tid; pp < NPLANES; pp += NT) {
            double ps = g_planeSS[pp];
            double r  = (double)g_row159[pp];
            double cc = (double)g_col159[pp];
            double e  = (double)g_e1599[pp];
            v[0] += ps; v[2] += r; v[3] += cc; v[6] += e;
            if ((pp % S) == S - 1) { v[1] += ps; v[4] += r; v[5] += cc; v[7] += e; }
        }
        #pragma unroll
        for (int q = 0; q < 8; q++) {
            #pragma unroll
            for (int off = 16; off > 0; off >>= 1)
                v[q] += __shfl_xor_sync(0xFFFFFFFFu, v[q], off);
        }
        if (lane == 0) {
            #pragma unroll
            for (int q = 0; q < 8; q++) sRed[wid][q] = v[q];
        }
        __syncthreads();
        if (tid == 0) {
            double t[8];
            #pragma unroll
            for (int q = 0; q < 8; q++) {
                t[q] = 0.0;
                #pragma unroll
                for (int w = 0; w < 10; w++) t[q] += sRed[w][q];
            }
            double ssOut = t[1] + t[2] + t[3] - t[4] - t[5] - t[6] + t[7];
            out[0] = (float)((t[0] - 0.99 * ssOut) / TOTAL_ELEMS);
        }
    } else {
        // ---- exact single-block fallback (never taken for dense masks) ----
        __shared__ int sMn[12], sMx[12];
        if (tid < 12) { sMn[tid] = S; sMx[tid] = -1; }
        __syncthreads();

        const int4* MM = (const int4*)mask;
        for (int i = tid; i < N4; i += NT) {
            int4 v = MM[i];
            if (v.x | v.y | v.z | v.w) {
                int bb  = i / BATCH4;
                int rem = i - bb * BATCH4;
                int d   = rem / PLANE4;
                int ip  = rem - d * PLANE4;
                int h   = ip / 40;
                int w0  = (ip - h * 40) * 4;
                atomicMin(&sMn[bb * 3 + 0], d); atomicMax(&sMx[bb * 3 + 0], d);
                atomicMin(&sMn[bb * 3 + 1], h); atomicMax(&sMx[bb * 3 + 1], h);
                if (v.x) { atomicMin(&sMn[bb * 3 + 2], w0 + 0); atomicMax(&sMx[bb * 3 + 2], w0 + 0); }
                if (v.y) { atomicMin(&sMn[bb * 3 + 2], w0 + 1); atomicMax(&sMx[bb * 3 + 2], w0 + 1); }
                if (v.z) { atomicMin(&sMn[bb * 3 + 2], w0 + 2); atomicMax(&sMx[bb * 3 + 2], w0 + 2); }
                if (v.w) { atomicMin(&sMn[bb * 3 + 2], w0 + 3); atomicMax(&sMx[bb * 3 + 2], w0 + 3); }
            }
        }
        __syncthreads();

        __shared__ int sLo[12], sHi[12];
        if (tid < 12) {
            int mn = (sMx[tid] >= 0) ? sMn[tid] : -1;
            int lo, hi;
            bbox_from(mn, sMx[tid], &lo, &hi);
            sLo[tid] = lo; sHi[tid] = hi;
        }
        __syncthreads();

        const float4* PP = (const float4*)pred;
        const float4* TT = (const float4*)truth;
        float fa = 0.0f;
        for (int i = tid; i < N4; i += NT) {
            float4 pv = PP[i];
            float4 tv = TT[i];
            int bb  = i / BATCH4;
            int rem = i - bb * BATCH4;
            int d   = rem / PLANE4;
            int ip  = rem - d * PLANE4;
            int h   = ip / 40;
            int w0  = (ip - h * 40) * 4;
            bool inDH = (d >= sLo[bb * 3]) && (d < sHi[bb * 3]) &&
                        (h >= sLo[bb * 3 + 1]) && (h < sHi[bb * 3 + 1]);
            int loW = sLo[bb * 3 + 2], hiW = sHi[bb * 3 + 2];
            float wx = (inDH && w0 + 0 >= loW && w0 + 0 < hiW) ? 1.0f : 0.01f;
            float wy = (inDH && w0 + 1 >= loW && w0 + 1 < hiW) ? 1.0f : 0.01f;
            float wz = (inDH && w0 + 2 >= loW && w0 + 2 < hiW) ? 1.0f : 0.01f;
            float ww = (inDH && w0 + 3 >= loW && w0 + 3 < hiW) ? 1.0f : 0.01f;
            float dx = pv.x - tv.x, dy = pv.y - tv.y, dz = pv.z - tv.z, dw = pv.w - tv.w;
            fa = fmaf(wx * dx, dx, fa);
            fa = fmaf(wy * dy, dy, fa);
            fa = fmaf(wz * dz, dz, fa);
            fa = fmaf(ww * dw, dw, fa);
        }
        #pragma unroll
        for (int off = 16; off > 0; off >>= 1)
            fa += __shfl_xor_sync(0xFFFFFFFFu, fa, off);
        if (lane == 0) wAcc[wid] = (double)fa;
        __syncthreads();
        if (tid == 0) {
            double s = 0.0;
            #pragma unroll
            for (int w = 0; w < 10; w++) s += wAcc[w];
            out[0] = (float)(s / TOTAL_ELEMS);
        }
    }

    // ---- reset scratch so the next graph replay starts from a clean state --
    __syncthreads();
    if (tid < 32) {
        ((unsigned char*)g_winD)[tid] = 0;
        ((unsigned char*)g_winH)[tid] = 0;
        ((unsigned char*)g_winW)[tid] = 0;
    }
    if (tid == 0) g_done = 0u;
}

extern "C" void kernel_launch(void* const* d_in, const int* in_sizes, int n_in,
                              void* d_out, int out_size) {
    const float* y_pred = (const float*)d_in[0];
    const float* y_true = (const float*)d_in[1];
    const int*   mask   = (const int*)d_in[2];
    float* out = (float*)d_out;

    k_all<<<NPLANES, NT>>>(y_pred, y_true, mask, out);
}